// round 5
// baseline (speedup 1.0000x reference)
#include <cuda_runtime.h>
#include <cuda_bf16.h>
#include <mma.h>
#include <cstdint>

using namespace nvcuda;

#define NN    6144
#define INF   256
#define NH    4
#define DHD   64
#define HD    256
#define NCOLS 576

// GEMM tiling (round-3 proven config)
#define BM 128
#define BN 192
#define BK 64
#define STAGES 3
#define KITERS (NN / BK)     // 96
#define GTHREADS 256

// smem stage layout (bytes)
#define A_LD    72           // elems per row (64 + 8 pad)
#define B_LD    200          // elems per row (192 + 8 pad)
#define A_BYTES (BM * A_LD * 2)          // 18432
#define B_BYTES (BK * B_LD * 2)          // 25600
#define STAGE_BYTES (A_BYTES + 2 * B_BYTES)   // 69632
#define SMEM_BYTES  (STAGES * STAGE_BYTES)    // 208896

// ---------------- scratch (static device globals) ----------------
__device__ float          g_h[NH][NN][DHD];
__device__ float          g_esrc[NH][NN];
__device__ float          g_esdst[NH][NN];
__device__ float          g_T[NH][DHD];
__device__ __nv_bfloat16  g_Bhi[NN][NCOLS];           // 7.1 MB, [k][n]
__device__ __nv_bfloat16  g_Blo[NN][NCOLS];           // 7.1 MB, [k][n]
__device__ float          g_C[NN][NCOLS];             // 14.2 MB

// ---------------- helpers ----------------
__device__ __forceinline__ uint32_t smem_u32(const void* p) {
    uint32_t a;
    asm("{ .reg .u64 t; cvta.to.shared.u64 t, %1; cvt.u32.u64 %0, t; }" : "=r"(a) : "l"(p));
    return a;
}
__device__ __forceinline__ void cp16(uint32_t dst, const void* src) {
    asm volatile("cp.async.cg.shared.global [%0], [%1], 16;" :: "r"(dst), "l"(src) : "memory");
}
__device__ __forceinline__ uint32_t pack2(int a, int b) {
    return (a > 0 ? 0x3F80u : 0u) | ((b > 0 ? 0x3F80u : 0u) << 16);
}

// ---------------- K1: h = x @ W + Wb (fp32 SIMT, float4 shared loads) ----------------
__global__ void k_h_gemm(const float* __restrict__ x, const float* __restrict__ W,
                         const float* __restrict__ Wb) {
    __shared__ float sA[16][68];   // row stride 272B (16B-aligned)
    __shared__ float sB[16][64];
    const int tid = threadIdx.x;
    const int tx = tid & 15;
    const int ty = tid >> 4;
    const int m0 = blockIdx.x * 64;
    const int head = blockIdx.y;

    float acc[4][4];
#pragma unroll
    for (int r = 0; r < 4; r++)
#pragma unroll
        for (int c = 0; c < 4; c++) acc[r][c] = 0.f;

    for (int k0 = 0; k0 < INF; k0 += 16) {
#pragma unroll
        for (int i = tid; i < 1024; i += 256) {
            int m = i >> 4, kk = i & 15;
            sA[kk][m] = x[(m0 + m) * INF + k0 + kk];
        }
#pragma unroll
        for (int i = tid; i < 1024; i += 256) {
            int kk = i >> 6, c = i & 63;
            sB[kk][c] = W[head * (INF * DHD) + (k0 + kk) * DHD + c];
        }
        __syncthreads();
#pragma unroll
        for (int kk = 0; kk < 16; kk++) {
            float4 av = *(const float4*)&sA[kk][ty * 4];
            float4 bv = *(const float4*)&sB[kk][tx * 4];
            float a4[4] = {av.x, av.y, av.z, av.w};
            float b4[4] = {bv.x, bv.y, bv.z, bv.w};
#pragma unroll
            for (int r = 0; r < 4; r++)
#pragma unroll
                for (int c = 0; c < 4; c++) acc[r][c] += a4[r] * b4[c];
        }
        __syncthreads();
    }
#pragma unroll
    for (int r = 0; r < 4; r++)
#pragma unroll
        for (int c = 0; c < 4; c++) {
            int d = tx * 4 + c;
            g_h[head][m0 + ty * 4 + r][d] = acc[r][c] + Wb[head * DHD + d];
        }
}

// ---------------- K2a: e^{s_src}, e^{s_dst} ----------------
__global__ void k_scores(const float* __restrict__ A, const float* __restrict__ Ab) {
    const int hd = blockIdx.x;
    const int wid = threadIdx.x >> 5, lane = threadIdx.x & 31;
    const int n = blockIdx.y * 8 + wid;
    const float h0 = g_h[hd][n][lane];
    const float h1 = g_h[hd][n][lane + 32];
    const float* Ah = A + hd * 2 * DHD;
    float ps = h0 * Ah[lane] + h1 * Ah[lane + 32];
    float pd = h0 * Ah[64 + lane] + h1 * Ah[96 + lane];
#pragma unroll
    for (int o = 16; o; o >>= 1) {
        ps += __shfl_xor_sync(0xffffffffu, ps, o);
        pd += __shfl_xor_sync(0xffffffffu, pd, o);
    }
    if (lane == 0) {
        g_esrc[hd][n]  = expf(ps + Ab[hd]);
        g_esdst[hd][n] = expf(pd);
    }
}

// ---------------- K2b: T[h][d] = sum_n h ----------------
__global__ void k_zeroT() { ((float*)g_T)[threadIdx.x] = 0.f; }

__global__ void k_T() {
    const int hd = blockIdx.x / 24;
    const int base = (blockIdx.x % 24) * 256;
    const int tid = threadIdx.x;
    const int d = tid & 63, rp = tid >> 6;
    float s = 0.f;
    for (int r = rp; r < 256; r += 4) s += g_h[hd][base + r][d];
    __shared__ float red[256];
    red[tid] = s;
    __syncthreads();
    if (rp == 0)
        atomicAdd(&g_T[hd][d], red[d] + red[64 + d] + red[128 + d] + red[192 + d]);
}

// ---------------- K2c: build B [k][n] split hi/lo ----------------
__global__ void k_buildB() {
    const int idx = blockIdx.x * 256 + threadIdx.x;   // over NN*NCOLS
    const int k = idx / NCOLS;
    const int col = idx - k * NCOLS;
    float v;
    if (col < 256) {
        int hd = col >> 6, d = col & 63;
        v = g_esdst[hd][k] * g_h[hd][k][d];
    } else if (col < 512) {
        int c2 = col - 256;
        int hd = c2 >> 6, d = c2 & 63;
        v = g_h[hd][k][d];
    } else if (col < 516) {
        v = g_esdst[col - 512][k];
    } else if (col == 516) {
        v = 1.0f;
    } else {
        v = 0.0f;
    }
    __nv_bfloat16 hi = __float2bfloat16(v);
    float lo = v - __bfloat162float(hi);
    g_Bhi[k][col] = hi;
    g_Blo[k][col] = __float2bfloat16(lo);
}

// ---------------- K3: pipelined wmma GEMM  C = adj @ (Bhi + Blo) ----------------
// A converted int32 -> bf16 in-kernel (no pre-pass). B via cp.async.
__device__ __forceinline__ void load_B_stage(uint32_t sb, int s, int k0, int n0, int tid) {
    const uint32_t bh_base = sb + s * STAGE_BYTES + A_BYTES;
    const uint32_t bl_base = bh_base + B_BYTES;
    // Bhi / Blo: 64 rows x 24 chunks(16B) = 1536 / 256 = 6 each
#pragma unroll
    for (int q = 0; q < 6; q++) {
        int idx = tid + q * GTHREADS;
        int row = idx / 24, c = idx - row * 24;
        cp16(bh_base + row * (B_LD * 2) + c * 16, &g_Bhi[k0 + row][n0 + c * 8]);
    }
#pragma unroll
    for (int q = 0; q < 6; q++) {
        int idx = tid + q * GTHREADS;
        int row = idx / 24, c = idx - row * 24;
        cp16(bl_base + row * (B_LD * 2) + c * 16, &g_Blo[k0 + row][n0 + c * 8]);
    }
    asm volatile("cp.async.commit_group;" ::: "memory");
}

// synchronous A fill (prologue): thread t -> row t>>1, cols [(t&1)*32, +32)
__device__ __forceinline__ void load_A_sync(char* smem, int s, int k0, int m0,
                                            const int* __restrict__ adj, int tid) {
    const int row = tid >> 1;
    const int ch  = (tid & 1) * 32;
    const int4* src = (const int4*)(adj + (size_t)(m0 + row) * NN + k0 + ch);
    uint32_t* dst = (uint32_t*)(smem + s * STAGE_BYTES + row * (A_LD * 2) + ch * 2);
#pragma unroll
    for (int q = 0; q < 8; q++) {
        int4 a = src[q];
        dst[q * 2 + 0] = pack2(a.x, a.y);
        dst[q * 2 + 1] = pack2(a.z, a.w);
    }
}

__global__ void __launch_bounds__(GTHREADS, 1) k_attn_gemm(const int* __restrict__ adj) {
    extern __shared__ char smem[];
    const uint32_t sb = smem_u32(smem);
    const int tid = threadIdx.x;
    const int wid = tid >> 5;
    const int wm = wid >> 2;          // 0..1  (64 rows each)
    const int wn = wid & 3;           // 0..3  (48 cols each)
    const int n0 = blockIdx.x * BN;
    const int m0 = blockIdx.y * BM;

    // A-conversion per-thread mapping
    const int arow = tid >> 1;
    const int ach  = (tid & 1) * 32;
    const int* asrc_row = adj + (size_t)(m0 + arow) * NN + ach;

    wmma::fragment<wmma::accumulator, 16, 16, 16, float> acc[4][3];
#pragma unroll
    for (int r = 0; r < 4; r++)
#pragma unroll
        for (int c = 0; c < 3; c++) wmma::fill_fragment(acc[r][c], 0.f);

    // prologue: stages 0,1 (A sync, B async)
    load_A_sync(smem, 0, 0, m0, adj, tid);
    load_A_sync(smem, 1, BK, m0, adj, tid);
    load_B_stage(sb, 0, 0, n0, tid);
    load_B_stage(sb, 1, BK, n0, tid);

    for (int i = 0; i < KITERS; i++) {
        const int s = i % STAGES;

        // issue A LDG (regs) + B cp.async for stage i+2
        int4 areg[8];
        const bool pf = (i + 2 < KITERS);
        if (pf) {
            const int4* src = (const int4*)(asrc_row + (i + 2) * BK);
#pragma unroll
            for (int q = 0; q < 8; q++) areg[q] = src[q];
            load_B_stage(sb, (i + 2) % STAGES, (i + 2) * BK, n0, tid);
        } else {
            asm volatile("cp.async.commit_group;" ::: "memory");
        }

        asm volatile("cp.async.wait_group 2;" ::: "memory");
        __syncthreads();

        const __nv_bfloat16* sA  = (const __nv_bfloat16*)(smem + s * STAGE_BYTES);
        const __nv_bfloat16* sBh = (const __nv_bfloat16*)(smem + s * STAGE_BYTES + A_BYTES);
        const __nv_bfloat16* sBl = (const __nv_bfloat16*)(smem + s * STAGE_BYTES + A_BYTES + B_BYTES);

#pragma unroll
        for (int kk = 0; kk < BK / 16; kk++) {
            wmma::fragment<wmma::matrix_a, 16, 16, 16, __nv_bfloat16, wmma::row_major> af[4];
#pragma unroll
            for (int r = 0; r < 4; r++)
                wmma::load_matrix_sync(af[r], sA + (wm * 64 + r * 16) * A_LD + kk * 16, A_LD);
#pragma unroll
            for (int c = 0; c < 3; c++) {
                wmma::fragment<wmma::matrix_b, 16, 16, 16, __nv_bfloat16, wmma::row_major> bf;
                wmma::load_matrix_sync(bf, sBh + (kk * 16) * B_LD + wn * 48 + c * 16, B_LD);
#pragma unroll
                for (int r = 0; r < 4; r++) wmma::mma_sync(acc[r][c], af[r], bf, acc[r][c]);
                wmma::load_matrix_sync(bf, sBl + (kk * 16) * B_LD + wn * 48 + c * 16, B_LD);
#pragma unroll
                for (int r = 0; r < 4; r++) wmma::mma_sync(acc[r][c], af[r], bf, acc[r][c]);
            }
        }

        // convert + STS A for stage i+2 (readers sync at iteration i+1's barrier)
        if (pf) {
            uint32_t* dst = (uint32_t*)(smem + ((i + 2) % STAGES) * STAGE_BYTES
                                        + arow * (A_LD * 2) + ach * 2);
#pragma unroll
            for (int q = 0; q < 8; q++) {
                dst[q * 2 + 0] = pack2(areg[q].x, areg[q].y);
                dst[q * 2 + 1] = pack2(areg[q].z, areg[q].w);
            }
        }
        __syncthreads();
    }

#pragma unroll
    for (int r = 0; r < 4; r++)
#pragma unroll
        for (int c = 0; c < 3; c++)
            wmma::store_matrix_sync(&g_C[m0 + wm * 64 + r * 16][n0 + wn * 48 + c * 16],
                                    acc[r][c], NCOLS, wmma::mem_row_major);
}

// ---------------- K4: epilogue ----------------
__global__ void k_epi(float* __restrict__ out) {
    const int idx = blockIdx.x * 256 + threadIdx.x;
    const int n = idx >> 8;
    const int c = idx & 255;
    const int hd = c >> 6, d = c & 63;
    const float es  = g_esrc[hd][n];
    const float u   = g_C[n][hd * 64 + d];
    const float v   = g_C[n][256 + hd * 64 + d];
    const float w   = g_C[n][512 + hd];
    const float deg = g_C[n][516];
    const float Z = es * w + ((float)NN - deg);
    out[idx] = (es * u + g_T[hd][d] - v) / Z;
}

// ---------------- launch ----------------
extern "C" void kernel_launch(void* const* d_in, const int* in_sizes, int n_in,
                              void* d_out, int out_size) {
    const float* x = nullptr; const int* adj = nullptr;
    const float* W = nullptr; const float* Wb = nullptr;
    const float* A = nullptr; const float* Ab = nullptr;
    for (int i = 0; i < n_in; i++) {
        switch (in_sizes[i]) {
            case NN * INF:        x   = (const float*)d_in[i]; break;
            case NH * INF * DHD:  W   = (const float*)d_in[i]; break;
            case NH * DHD:        Wb  = (const float*)d_in[i]; break;
            case NH * 2 * DHD:    A   = (const float*)d_in[i]; break;
            case NH:              Ab  = (const float*)d_in[i]; break;
            default:
                if (in_sizes[i] == NN * NN) adj = (const int*)d_in[i];
                break;
        }
    }
    float* out = (float*)d_out;

    cudaFuncSetAttribute(k_attn_gemm, cudaFuncAttributeMaxDynamicSharedMemorySize, SMEM_BYTES);

    k_h_gemm<<<dim3(NN / 64, NH), 256>>>(x, W, Wb);
    k_scores<<<dim3(NH, NN / 8), 256>>>(A, Ab);
    k_zeroT<<<1, 256>>>();
    k_T<<<NH * 24, 256>>>();
    k_buildB<<<(NN * NCOLS) / 256, 256>>>();
    k_attn_gemm<<<dim3(NCOLS / BN, NN / BM), GTHREADS, SMEM_BYTES>>>(adj);
    k_epi<<<(NN * HD) / 256, 256>>>(out);
}

// round 6
// speedup vs baseline: 1.2989x; 1.2989x over previous
#include <cuda_runtime.h>
#include <cuda_bf16.h>
#include <mma.h>
#include <cstdint>

using namespace nvcuda;

#define NN    6144
#define INF   256
#define NH    4
#define DHD   64
#define HD    256
#define NCOLS 576

// GEMM tiling (round-3 proven config)
#define BM 128
#define BN 192
#define BK 64
#define STAGES 3
#define KITERS (NN / BK)     // 96
#define GTHREADS 256

// smem stage layout (bytes)
#define A_LD    72
#define B_LD    200
#define A_BYTES (BM * A_LD * 2)          // 18432
#define B_BYTES (BK * B_LD * 2)          // 25600
#define STAGE_BYTES (A_BYTES + 2 * B_BYTES)   // 69632
#define SMEM_BYTES  (STAGES * STAGE_BYTES)    // 208896

// ---------------- scratch ----------------
__device__ float          g_h[NH][NN][DHD];
__device__ float          g_esrc[NH][NN];
__device__ float          g_esdst[NH][NN];
__device__ float          g_T[NH][DHD];
__device__ __nv_bfloat16  g_adjb[(size_t)NN * NN];    // 75.5 MB, [m][k]
__device__ __nv_bfloat16  g_Bhi[NN][NCOLS];
__device__ __nv_bfloat16  g_Blo[NN][NCOLS];
__device__ float          g_C[NN][NCOLS];

// ---------------- helpers ----------------
__device__ __forceinline__ uint32_t smem_u32(const void* p) {
    uint32_t a;
    asm("{ .reg .u64 t; cvta.to.shared.u64 t, %1; cvt.u32.u64 %0, t; }" : "=r"(a) : "l"(p));
    return a;
}
__device__ __forceinline__ void cp16(uint32_t dst, const void* src) {
    asm volatile("cp.async.cg.shared.global [%0], [%1], 16;" :: "r"(dst), "l"(src) : "memory");
}
__device__ __forceinline__ uint32_t pack2(int a, int b) {
    return (a > 0 ? 0x3F80u : 0u) | ((b > 0 ? 0x3F80u : 0u) << 16);
}

// ---------------- K1: merged  h = x@W + Wb  (blocks 0..383)  ||  adj->bf16 (rest) ----------------
#define HBLOCKS (NN / 64 * NH)     // 384
#define CVTBLKS ((int)((size_t)NN * NN / 2048))   // 18432

__global__ void k_pre(const float* __restrict__ x, const float* __restrict__ W,
                      const float* __restrict__ Wb, const int* __restrict__ adj) {
    __shared__ float sA[16][68];
    __shared__ float sB[16][64];
    const int bx = blockIdx.x;
    const int tid = threadIdx.x;

    if (bx >= HBLOCKS) {
        // ---- adj int32 -> bf16 ----
        size_t i = (size_t)(bx - HBLOCKS) * 2048 + (size_t)tid * 8;
        const int4* p = (const int4*)(adj + i);
        int4 a = p[0], b = p[1];
        *(uint4*)(&g_adjb[i]) = make_uint4(pack2(a.x, a.y), pack2(a.z, a.w),
                                           pack2(b.x, b.y), pack2(b.z, b.w));
        return;
    }

    // ---- h gemm ----
    const int head = bx & 3;
    const int m0 = (bx >> 2) * 64;
    const int tx = tid & 15;
    const int ty = tid >> 4;

    float acc[4][4];
#pragma unroll
    for (int r = 0; r < 4; r++)
#pragma unroll
        for (int c = 0; c < 4; c++) acc[r][c] = 0.f;

    for (int k0 = 0; k0 < INF; k0 += 16) {
#pragma unroll
        for (int i = tid; i < 1024; i += 256) {
            int m = i >> 4, kk = i & 15;
            sA[kk][m] = x[(m0 + m) * INF + k0 + kk];
        }
#pragma unroll
        for (int i = tid; i < 1024; i += 256) {
            int kk = i >> 6, c = i & 63;
            sB[kk][c] = W[head * (INF * DHD) + (k0 + kk) * DHD + c];
        }
        __syncthreads();
#pragma unroll
        for (int kk = 0; kk < 16; kk++) {
            float4 av = *(const float4*)&sA[kk][ty * 4];
            float4 bv = *(const float4*)&sB[kk][tx * 4];
            float a4[4] = {av.x, av.y, av.z, av.w};
            float b4[4] = {bv.x, bv.y, bv.z, bv.w};
#pragma unroll
            for (int r = 0; r < 4; r++)
#pragma unroll
                for (int c = 0; c < 4; c++) acc[r][c] += a4[r] * b4[c];
        }
        __syncthreads();
    }
#pragma unroll
    for (int r = 0; r < 4; r++)
#pragma unroll
        for (int c = 0; c < 4; c++) {
            int d = tx * 4 + c;
            g_h[head][m0 + ty * 4 + r][d] = acc[r][c] + Wb[head * DHD + d];
        }
}

// ---------------- K2: scores (+ zero g_T for next kernel) ----------------
__global__ void k_scores(const float* __restrict__ A, const float* __restrict__ Ab) {
    const int hd = blockIdx.x;
    if (hd == 0 && blockIdx.y == 0) ((float*)g_T)[threadIdx.x] = 0.f;
    const int wid = threadIdx.x >> 5, lane = threadIdx.x & 31;
    const int n = blockIdx.y * 8 + wid;
    const float h0 = g_h[hd][n][lane];
    const float h1 = g_h[hd][n][lane + 32];
    const float* Ah = A + hd * 2 * DHD;
    float ps = h0 * Ah[lane] + h1 * Ah[lane + 32];
    float pd = h0 * Ah[64 + lane] + h1 * Ah[96 + lane];
#pragma unroll
    for (int o = 16; o; o >>= 1) {
        ps += __shfl_xor_sync(0xffffffffu, ps, o);
        pd += __shfl_xor_sync(0xffffffffu, pd, o);
    }
    if (lane == 0) {
        g_esrc[hd][n]  = expf(ps + Ab[hd]);
        g_esdst[hd][n] = expf(pd);
    }
}

// ---------------- K3: merged  T-reduce (blocks 0..95)  ||  buildB (rest) ----------------
#define TBLOCKS 96
#define BBLKS   ((NN * NCOLS) / 256)    // 13824

__global__ void k_T_buildB() {
    const int bx = blockIdx.x;
    const int tid = threadIdx.x;

    if (bx < TBLOCKS) {
        const int hd = bx / 24;
        const int base = (bx % 24) * 256;
        const int d = tid & 63, rp = tid >> 6;
        float s = 0.f;
        for (int r = rp; r < 256; r += 4) s += g_h[hd][base + r][d];
        __shared__ float red[256];
        red[tid] = s;
        __syncthreads();
        if (rp == 0)
            atomicAdd(&g_T[hd][d], red[d] + red[64 + d] + red[128 + d] + red[192 + d]);
        return;
    }

    const int idx = (bx - TBLOCKS) * 256 + tid;
    const int k = idx / NCOLS;
    const int col = idx - k * NCOLS;
    float v;
    if (col < 256) {
        int hd = col >> 6, d = col & 63;
        v = g_esdst[hd][k] * g_h[hd][k][d];
    } else if (col < 512) {
        int c2 = col - 256;
        int hd = c2 >> 6, d = c2 & 63;
        v = g_h[hd][k][d];
    } else if (col < 516) {
        v = g_esdst[col - 512][k];
    } else if (col == 516) {
        v = 1.0f;
    } else {
        v = 0.0f;
    }
    __nv_bfloat16 hi = __float2bfloat16(v);
    float lo = v - __bfloat162float(hi);
    g_Bhi[k][col] = hi;
    g_Blo[k][col] = __float2bfloat16(lo);
}

// ---------------- K4: pipelined wmma GEMM  C = adj @ (Bhi + Blo) ----------------
__device__ __forceinline__ void load_stage(uint32_t sb, int s, int k0, int m0, int n0,
                                           const __nv_bfloat16* __restrict__ adjb, int tid) {
    const uint32_t a_base  = sb + s * STAGE_BYTES;
    const uint32_t bh_base = a_base + A_BYTES;
    const uint32_t bl_base = bh_base + B_BYTES;
#pragma unroll
    for (int q = 0; q < 4; q++) {
        int idx = tid + q * 256;
        int row = idx >> 3, c = idx & 7;
        cp16(a_base + row * (A_LD * 2) + c * 16,
             adjb + (size_t)(m0 + row) * NN + k0 + c * 8);
    }
#pragma unroll
    for (int q = 0; q < 6; q++) {
        int idx = tid + q * 256;
        int row = idx / 24, c = idx - row * 24;
        cp16(bh_base + row * (B_LD * 2) + c * 16, &g_Bhi[k0 + row][n0 + c * 8]);
    }
#pragma unroll
    for (int q = 0; q < 6; q++) {
        int idx = tid + q * 256;
        int row = idx / 24, c = idx - row * 24;
        cp16(bl_base + row * (B_LD * 2) + c * 16, &g_Blo[k0 + row][n0 + c * 8]);
    }
    asm volatile("cp.async.commit_group;" ::: "memory");
}

__global__ void __launch_bounds__(GTHREADS, 1) k_attn_gemm(const __nv_bfloat16* __restrict__ adjb) {
    extern __shared__ char smem[];
    const uint32_t sb = smem_u32(smem);
    const int tid = threadIdx.x;
    const int wid = tid >> 5;
    const int wm = wid >> 2;          // 0..1  (64 rows each)
    const int wn = wid & 3;           // 0..3  (48 cols each)
    const int n0 = blockIdx.x * BN;
    const int m0 = blockIdx.y * BM;

    wmma::fragment<wmma::accumulator, 16, 16, 16, float> acc[4][3];
#pragma unroll
    for (int r = 0; r < 4; r++)
#pragma unroll
        for (int c = 0; c < 3; c++) wmma::fill_fragment(acc[r][c], 0.f);

    // prologue: stages 0, 1
    load_stage(sb, 0, 0, m0, n0, adjb, tid);
    load_stage(sb, 1, BK, m0, n0, adjb, tid);

    for (int i = 0; i < KITERS; i++) {
        const int s = i % STAGES;

        // stage i complete when <=1 groups outstanding
        asm volatile("cp.async.wait_group 1;" ::: "memory");
        __syncthreads();
        // all threads finished reading stage (i-1) == (i+2)%3  ->  safe to overwrite now
        if (i + 2 < KITERS)
            load_stage(sb, (i + 2) % STAGES, (i + 2) * BK, m0, n0, adjb, tid);
        else
            asm volatile("cp.async.commit_group;" ::: "memory");

        const __nv_bfloat16* sA  = (const __nv_bfloat16*)(smem + s * STAGE_BYTES);
        const __nv_bfloat16* sBh = (const __nv_bfloat16*)(smem + s * STAGE_BYTES + A_BYTES);
        const __nv_bfloat16* sBl = (const __nv_bfloat16*)(smem + s * STAGE_BYTES + A_BYTES + B_BYTES);

#pragma unroll
        for (int kk = 0; kk < BK / 16; kk++) {
            wmma::fragment<wmma::matrix_a, 16, 16, 16, __nv_bfloat16, wmma::row_major> af[4];
#pragma unroll
            for (int r = 0; r < 4; r++)
                wmma::load_matrix_sync(af[r], sA + (wm * 64 + r * 16) * A_LD + kk * 16, A_LD);
#pragma unroll
            for (int c = 0; c < 3; c++) {
                wmma::fragment<wmma::matrix_b, 16, 16, 16, __nv_bfloat16, wmma::row_major> bf;
                wmma::load_matrix_sync(bf, sBh + (kk * 16) * B_LD + wn * 48 + c * 16, B_LD);
#pragma unroll
                for (int r = 0; r < 4; r++) wmma::mma_sync(acc[r][c], af[r], bf, acc[r][c]);
                wmma::load_matrix_sync(bf, sBl + (kk * 16) * B_LD + wn * 48 + c * 16, B_LD);
#pragma unroll
                for (int r = 0; r < 4; r++) wmma::mma_sync(acc[r][c], af[r], bf, acc[r][c]);
            }
        }
    }

#pragma unroll
    for (int r = 0; r < 4; r++)
#pragma unroll
        for (int c = 0; c < 3; c++)
            wmma::store_matrix_sync(&g_C[m0 + wm * 64 + r * 16][n0 + wn * 48 + c * 16],
                                    acc[r][c], NCOLS, wmma::mem_row_major);
}

// ---------------- K5: epilogue ----------------
__global__ void k_epi(float* __restrict__ out) {
    const int idx = blockIdx.x * 256 + threadIdx.x;
    const int n = idx >> 8;
    const int c = idx & 255;
    const int hd = c >> 6, d = c & 63;
    const float es  = g_esrc[hd][n];
    const float u   = g_C[n][hd * 64 + d];
    const float v   = g_C[n][256 + hd * 64 + d];
    const float w   = g_C[n][512 + hd];
    const float deg = g_C[n][516];
    const float Z = es * w + ((float)NN - deg);
    out[idx] = (es * u + g_T[hd][d] - v) / Z;
}

// ---------------- launch ----------------
extern "C" void kernel_launch(void* const* d_in, const int* in_sizes, int n_in,
                              void* d_out, int out_size) {
    const float* x = nullptr; const int* adj = nullptr;
    const float* W = nullptr; const float* Wb = nullptr;
    const float* A = nullptr; const float* Ab = nullptr;
    for (int i = 0; i < n_in; i++) {
        switch (in_sizes[i]) {
            case NN * INF:        x   = (const float*)d_in[i]; break;
            case NH * INF * DHD:  W   = (const float*)d_in[i]; break;
            case NH * DHD:        Wb  = (const float*)d_in[i]; break;
            case NH * 2 * DHD:    A   = (const float*)d_in[i]; break;
            case NH:              Ab  = (const float*)d_in[i]; break;
            default:
                if (in_sizes[i] == NN * NN) adj = (const int*)d_in[i];
                break;
        }
    }
    float* out = (float*)d_out;

    cudaFuncSetAttribute(k_attn_gemm, cudaFuncAttributeMaxDynamicSharedMemorySize, SMEM_BYTES);

    __nv_bfloat16* adjb_ptr = nullptr;
    cudaGetSymbolAddress((void**)&adjb_ptr, g_adjb);

    k_pre<<<HBLOCKS + CVTBLKS, 256>>>(x, W, Wb, adj);
    k_scores<<<dim3(NH, NN / 8), 256>>>(A, Ab);
    k_T_buildB<<<TBLOCKS + BBLKS, 256>>>();
    k_attn_gemm<<<dim3(NCOLS / BN, NN / BM), GTHREADS, SMEM_BYTES>>>(adjb_ptr);
    k_epi<<<(NN * HD) / 256, 256>>>(out);
}